// round 3
// baseline (speedup 1.0000x reference)
#include <cuda_runtime.h>

#define NN 50000
#define EE 800000
#define DD 128

// ---------------- scratch (__device__ globals; no runtime allocation) ------
__device__ float g_q[NN * DD];
__device__ float g_k[NN * DD];
__device__ float g_v[NN * DD];
__device__ float g_h[NN * DD];
__device__ int   g_cnt[NN];
__device__ int   g_off[NN + 1];
__device__ int   g_csrc[EE];
__device__ int   g_stride;     // 1 = int32 indices, 2 = int64 (read low word)

// ---------------- dtype sniffer -------------------------------------------
// If indices are little-endian int64 with values < 2^31, every odd 32-bit
// word is 0. If int32, odd words are random node ids (nonzero w.h.p.).
__global__ void sniff_kernel(const int* __restrict__ dstw)
{
    __shared__ int any_nonzero;
    if (threadIdx.x == 0) any_nonzero = 0;
    __syncthreads();
    int v = dstw[2 * threadIdx.x + 1];   // odd words, first 512 pairs
    if (v != 0) atomicOr(&any_nonzero, 1);
    __syncthreads();
    if (threadIdx.x == 0) g_stride = any_nonzero ? 1 : 2;
}

// ---------------- GEMM core: C tile = X[64,128] @ W[128,128] + b -----------
// 48KB static smem, two K-halves. 256 threads, 8x4 register micro-tile.
template <int SEL>
__global__ void gemm128_kernel(const float* __restrict__ X,
                               const float* __restrict__ W,
                               const float* __restrict__ b,
                               float* __restrict__ Cout)
{
    __shared__ float Xs[64 * 64];    // 16 KB
    __shared__ float Ws[64 * 128];   // 32 KB

    float* C;
    if      (SEL == 0) C = g_q;
    else if (SEL == 1) C = g_k;
    else if (SEL == 2) C = g_v;
    else               C = Cout;

    const float* Xin = (SEL == 3) ? g_h : X;

    const int tid  = threadIdx.x;       // 0..255
    const int row0 = blockIdx.x * 64;

    const int tx = tid & 31;   // col group (float4)
    const int ty = tid >> 5;   // row group (0..7)
    const int c0 = tx * 4;
    const int r0 = ty * 8;

    float acc[8][4];
#pragma unroll
    for (int i = 0; i < 8; i++)
#pragma unroll
        for (int j = 0; j < 4; j++) acc[i][j] = 0.f;

#pragma unroll
    for (int kk = 0; kk < 2; kk++) {
        // load X half-tile: 64 rows x 64 cols = 1024 float4
        for (int i = tid; i < 64 * 16; i += 256) {
            int r  = i >> 4;
            int c4 = i & 15;
            int gr = row0 + r;
            float4 vx = make_float4(0.f, 0.f, 0.f, 0.f);
            if (gr < NN) vx = *(const float4*)&Xin[gr * DD + kk * 64 + c4 * 4];
            *(float4*)&Xs[r * 64 + c4 * 4] = vx;
        }
        // load W half: 64 rows x 128 cols = 2048 float4
        for (int i = tid; i < 64 * 32; i += 256) {
            int r  = i >> 5;
            int c4 = i & 31;
            *(float4*)&Ws[r * DD + c4 * 4] =
                *(const float4*)&W[(kk * 64 + r) * DD + c4 * 4];
        }
        __syncthreads();

#pragma unroll 8
        for (int k = 0; k < 64; k++) {
            float4 wv = *(float4*)&Ws[k * DD + c0];
            float xv[8];
#pragma unroll
            for (int i = 0; i < 8; i++) xv[i] = Xs[(r0 + i) * 64 + k];
#pragma unroll
            for (int i = 0; i < 8; i++) {
                acc[i][0] += xv[i] * wv.x;
                acc[i][1] += xv[i] * wv.y;
                acc[i][2] += xv[i] * wv.z;
                acc[i][3] += xv[i] * wv.w;
            }
        }
        __syncthreads();
    }

    const float4 bv = *(const float4*)&b[c0];
#pragma unroll
    for (int i = 0; i < 8; i++) {
        int gr = row0 + r0 + i;
        if (gr < NN) {
            float4 o = make_float4(acc[i][0] + bv.x, acc[i][1] + bv.y,
                                   acc[i][2] + bv.z, acc[i][3] + bv.w);
            *(float4*)&C[gr * DD + c0] = o;
        }
    }
}

// ---------------- CSR build ------------------------------------------------
__global__ void zero_cnt_kernel()
{
    int i = blockIdx.x * blockDim.x + threadIdx.x;
    if (i < NN) g_cnt[i] = 0;
}

__global__ void hist_kernel(const int* __restrict__ dstw)
{
    int e = blockIdx.x * blockDim.x + threadIdx.x;
    if (e < EE) {
        int d = dstw[e * g_stride];
        atomicAdd(&g_cnt[d], 1);
    }
}

// single-block inclusive scan over 50000 counts -> g_off
__global__ void scan_kernel()
{
    __shared__ int sh[1024];
    __shared__ int carry;
    if (threadIdx.x == 0) carry = 0;
    __syncthreads();
    for (int base = 0; base < NN; base += 1024) {
        int i   = base + (int)threadIdx.x;
        int val = (i < NN) ? g_cnt[i] : 0;
        sh[threadIdx.x] = val;
        __syncthreads();
        for (int o = 1; o < 1024; o <<= 1) {
            int t = (threadIdx.x >= (unsigned)o) ? sh[threadIdx.x - o] : 0;
            __syncthreads();
            sh[threadIdx.x] += t;
            __syncthreads();
        }
        if (i < NN) g_off[i + 1] = sh[threadIdx.x] + carry;
        __syncthreads();
        if (threadIdx.x == 0) carry += sh[1023];
        __syncthreads();
    }
    if (threadIdx.x == 0) g_off[0] = 0;
}

__global__ void scatter_kernel(const int* __restrict__ srcw,
                               const int* __restrict__ dstw)
{
    int e = blockIdx.x * blockDim.x + threadIdx.x;
    if (e < EE) {
        int st  = g_stride;
        int d   = dstw[e * st];
        int s   = srcw[e * st];
        int pos = atomicAdd(&g_cnt[d], 1);
        g_csrc[g_off[d] + pos] = s;
    }
}

// ---------------- aggregation: warp per destination node -------------------
__global__ void agg_kernel()
{
    int w    = (blockIdx.x * blockDim.x + threadIdx.x) >> 5;
    int lane = threadIdx.x & 31;
    if (w >= NN) return;

    const float4 q4 = *(const float4*)&g_q[w * DD + lane * 4];
    const float qx = q4.x * 0.25f;   // fold 1/sqrt(d_k)=0.25 into q
    const float qy = q4.y * 0.25f;
    const float qz = q4.z * 0.25f;
    const float qw = q4.w * 0.25f;

    float zx = 0.f, zy = 0.f, zz = 0.f, zw = 0.f;
    float ax = 0.f, ay = 0.f, az = 0.f, aw = 0.f;

    const int beg = g_off[w];
    const int end = g_off[w + 1];

    for (int j0 = beg; j0 < end; j0 += 32) {
        int myS = (j0 + lane < end) ? g_csrc[j0 + lane] : 0;
        int cnt = min(32, end - j0);
        for (int t = 0; t < cnt; t++) {
            int s = __shfl_sync(0xffffffffu, myS, t);
            const float4 kk = *(const float4*)&g_k[s * DD + lane * 4];
            const float4 vv = *(const float4*)&g_v[s * DD + lane * 4];
            float mx = __expf(kk.x * qx);
            float my = __expf(kk.y * qy);
            float mz = __expf(kk.z * qz);
            float mw = __expf(kk.w * qw);
            zx += mx; zy += my; zz += mz; zw += mw;
            ax += mx * vv.x;
            ay += my * vv.y;
            az += mz * vv.z;
            aw += mw * vv.w;
        }
    }

    float4 o = make_float4(ax / zx, ay / zy, az / zz, aw / zw);
    *(float4*)&g_h[w * DD + lane * 4] = o;
}

// ---------------- launch ---------------------------------------------------
extern "C" void kernel_launch(void* const* d_in, const int* in_sizes, int n_in,
                              void* d_out, int out_size)
{
    const float* x   = (const float*)d_in[0];
    const int*   src = (const int*)d_in[1];   // int32 or int64 words; sniffed
    const int*   dst = (const int*)d_in[2];
    const float* Wq  = (const float*)d_in[3];
    const float* bq  = (const float*)d_in[4];
    const float* Wk  = (const float*)d_in[5];
    const float* bk  = (const float*)d_in[6];
    const float* Wv  = (const float*)d_in[7];
    const float* bv  = (const float*)d_in[8];
    const float* Wo  = (const float*)d_in[9];
    const float* bo  = (const float*)d_in[10];
    float*       out = (float*)d_out;

    const int gemm_blocks = (NN + 63) / 64;        // 782
    const int zero_blocks = (NN + 255) / 256;      // 196
    const int edge_blocks = (EE + 255) / 256;      // 3125
    const int agg_blocks  = (NN * 32 + 255) / 256; // 6250

    // detect index dtype (int32 vs int64)
    sniff_kernel<<<1, 512>>>(dst);

    // projections (write g_q / g_k / g_v internally)
    gemm128_kernel<0><<<gemm_blocks, 256>>>(x, Wq, bq, nullptr);
    gemm128_kernel<1><<<gemm_blocks, 256>>>(x, Wk, bk, nullptr);
    gemm128_kernel<2><<<gemm_blocks, 256>>>(x, Wv, bv, nullptr);

    // CSR by dst
    zero_cnt_kernel<<<zero_blocks, 256>>>();
    hist_kernel<<<edge_blocks, 256>>>(dst);
    scan_kernel<<<1, 1024>>>();
    zero_cnt_kernel<<<zero_blocks, 256>>>();
    scatter_kernel<<<edge_blocks, 256>>>(src, dst);

    // edge softmax-aggregate
    agg_kernel<<<agg_blocks, 256>>>();

    // output projection (reads g_h internally, writes d_out)
    gemm128_kernel<3><<<gemm_blocks, 256>>>(nullptr, Wo, bo, out);
}